// round 16
// baseline (speedup 1.0000x reference)
#include <cuda_runtime.h>
#include <cuda_fp16.h>
#include <math.h>
#include <stdint.h>

// Problem constants
#define SEQ    2048
#define DMODEL 1024
#define NH     16
#define NKV    4
#define HD     64
#define QKVN   1536         // fused Q(1024) + K(256) + V(256)
#define KVW    256          // NKV*HD

// ---------------------------------------------------------------------------
// Scratch (device globals)
// ---------------------------------------------------------------------------
__device__ __half g_x16[SEQ * DMODEL];
__device__ __half g_Wqkv16[DMODEL * QKVN];
__device__ __half g_Wo16[DMODEL * DMODEL];
__device__ float  g_QKV[SEQ * QKVN];
__device__ __half g_O16[SEQ * DMODEL];
__device__ __half g_Qh[SEQ * DMODEL];          // pre-scaled by 1/8
__device__ __half g_Kh[SEQ * KVW];
__device__ __half g_Vh[SEQ * KVW];

__device__ __forceinline__ uint32_t smem_u32(const void* p) {
    return (uint32_t)__cvta_generic_to_shared(p);
}

// ---------------------------------------------------------------------------
// cp.async helpers
// ---------------------------------------------------------------------------
__device__ __forceinline__ void cp_async16(uint32_t dst, const void* src) {
    asm volatile("cp.async.cg.shared.global [%0], [%1], 16;"
                 :: "r"(dst), "l"(src));
}
__device__ __forceinline__ void cp_commit() {
    asm volatile("cp.async.commit_group;");
}
template <int N>
__device__ __forceinline__ void cp_wait() {
    asm volatile("cp.async.wait_group %0;" :: "n"(N));
}

// ---------------------------------------------------------------------------
// Converts
// ---------------------------------------------------------------------------
__global__ void conv_f16_kernel(const float* __restrict__ in,
                                __half* __restrict__ out, int n) {
    int i = blockIdx.x * blockDim.x + threadIdx.x;
    if (i < n) out[i] = __float2half(in[i]);
}

__global__ void conv_wqkv_kernel(const float* __restrict__ Wq,
                                 const float* __restrict__ Wk,
                                 const float* __restrict__ Wv,
                                 __half* __restrict__ out) {
    int i = blockIdx.x * blockDim.x + threadIdx.x;
    if (i >= DMODEL * QKVN) return;
    int k = i / QKVN, n = i % QKVN;
    float v;
    if (n < 1024)       v = Wq[k * 1024 + n];
    else if (n < 1280)  v = Wk[k * 256 + (n - 1024)];
    else                v = Wv[k * 256 + (n - 1280)];
    out[i] = __float2half(v);
}

// ---------------------------------------------------------------------------
// HMMA GEMM (R8-proven 2-stage cp.async), templated on CTA N-tile.
// ---------------------------------------------------------------------------
#define BM 128
#define BK 32
#define ASTR 40      // halves

__device__ __forceinline__ void ldsm_x4(uint32_t* r, uint32_t addr) {
    asm volatile("ldmatrix.sync.aligned.m8n8.x4.shared.b16 {%0,%1,%2,%3}, [%4];"
                 : "=r"(r[0]), "=r"(r[1]), "=r"(r[2]), "=r"(r[3]) : "r"(addr));
}
__device__ __forceinline__ void ldsm_x4_trans(uint32_t* r, uint32_t addr) {
    asm volatile("ldmatrix.sync.aligned.m8n8.x4.trans.shared.b16 {%0,%1,%2,%3}, [%4];"
                 : "=r"(r[0]), "=r"(r[1]), "=r"(r[2]), "=r"(r[3]) : "r"(addr));
}
__device__ __forceinline__ void mma16816(float* c, const uint32_t* a,
                                         uint32_t b0, uint32_t b1) {
    asm volatile(
        "mma.sync.aligned.m16n8k16.row.col.f32.f16.f16.f32 "
        "{%0,%1,%2,%3}, {%4,%5,%6,%7}, {%8,%9}, {%0,%1,%2,%3};"
        : "+f"(c[0]), "+f"(c[1]), "+f"(c[2]), "+f"(c[3])
        : "r"(a[0]), "r"(a[1]), "r"(a[2]), "r"(a[3]), "r"(b0), "r"(b1));
}

template <int TBN>
__global__ __launch_bounds__(256)
void gemm_hmma_kernel(const __half* __restrict__ A,
                      const __half* __restrict__ B,
                      float* __restrict__ C, int M, int N, int K) {
    constexpr int BSTRT = TBN + 8;
    constexpr int WN    = TBN / 4;
    constexpr int FN    = WN / 8;
    constexpr int P16   = WN / 16;
    constexpr int COLS8 = TBN / 8;
    constexpr int BRPI  = 256 / COLS8;

    __shared__ __half As[2][BM * ASTR];
    __shared__ __half Bs[2][BK * BSTRT];

    const int tid = threadIdx.x;
    const int lane = tid & 31;
    const int wid = tid >> 5;
    const int wm0 = (wid >> 2) * 64;
    const int wn0 = (wid & 3) * WN;
    const int row0 = blockIdx.y * BM;
    const int col0 = blockIdx.x * TBN;

    const int ra = tid >> 2, ca = tid & 3;
    const int rb = tid / COLS8, cb = tid % COLS8;

    float acc[4][FN][4];
    #pragma unroll
    for (int i = 0; i < 4; i++)
        #pragma unroll
        for (int j = 0; j < FN; j++)
            #pragma unroll
            for (int k = 0; k < 4; k++) acc[i][j][k] = 0.f;

    const uint32_t as0 = smem_u32(As[0]), as1 = smem_u32(As[1]);
    const uint32_t bs0 = smem_u32(Bs[0]), bs1 = smem_u32(Bs[1]);

    const int a_lrow = lane & 15, a_lcol = (lane >> 4) << 3;
    const int b_krow = lane & 15, b_ncol = (lane >> 4) << 3;

    const int nchunks = K / BK;

    auto load_stage = [&](uint32_t asb, uint32_t bsb, int c) {
        int k0 = c * BK;
        cp_async16(asb + 2u * (ra * ASTR + ca * 8),
                   A + (size_t)(row0 + ra) * K + k0 + ca * 8);
        cp_async16(asb + 2u * ((ra + 64) * ASTR + ca * 8),
                   A + (size_t)(row0 + ra + 64) * K + k0 + ca * 8);
        #pragma unroll
        for (int r = 0; r < BK; r += BRPI) {
            cp_async16(bsb + 2u * ((rb + r) * BSTRT + cb * 8),
                       B + (size_t)(k0 + rb + r) * N + col0 + cb * 8);
        }
    };

    load_stage(as0, bs0, 0);
    cp_commit();

    for (int c = 0; c < nchunks; c++) {
        const uint32_t asb = (c & 1) ? as1 : as0;
        const uint32_t bsb = (c & 1) ? bs1 : bs0;
        if (c + 1 < nchunks) {
            load_stage((c & 1) ? as0 : as1, (c & 1) ? bs0 : bs1, c + 1);
            cp_commit();
            cp_wait<1>();
        } else {
            cp_wait<0>();
        }
        __syncthreads();

        #pragma unroll
        for (int ks = 0; ks < 2; ks++) {
            uint32_t af[4][4], bf[P16][4];
            #pragma unroll
            for (int fm = 0; fm < 4; fm++) {
                uint32_t addr = asb +
                    2u * ((wm0 + fm * 16 + a_lrow) * ASTR + ks * 16 + a_lcol);
                ldsm_x4(af[fm], addr);
            }
            #pragma unroll
            for (int p = 0; p < P16; p++) {
                uint32_t addr = bsb +
                    2u * ((ks * 16 + b_krow) * BSTRT + wn0 + p * 16 + b_ncol);
                ldsm_x4_trans(bf[p], addr);
            }
            #pragma unroll
            for (int fm = 0; fm < 4; fm++)
                #pragma unroll
                for (int fn = 0; fn < FN; fn++)
                    mma16816(acc[fm][fn], af[fm],
                             bf[fn >> 1][(fn & 1) * 2],
                             bf[fn >> 1][(fn & 1) * 2 + 1]);
        }
        __syncthreads();
    }

    const int g = lane >> 2, t = lane & 3;
    #pragma unroll
    for (int fm = 0; fm < 4; fm++) {
        #pragma unroll
        for (int fn = 0; fn < FN; fn++) {
            int r = row0 + wm0 + fm * 16 + g;
            int cc = col0 + wn0 + fn * 8 + 2 * t;
            *(float2*)(C + (size_t)r * N + cc) =
                make_float2(acc[fm][fn][0], acc[fm][fn][1]);
            *(float2*)(C + (size_t)(r + 8) * N + cc) =
                make_float2(acc[fm][fn][2], acc[fm][fn][3]);
        }
    }
}

// ---------------------------------------------------------------------------
// RoPE + fp16 convert with optional pre-scale (Q: 1/8, K: 1).
// ---------------------------------------------------------------------------
__global__ void rope_conv_kernel(const float* __restrict__ QKV,
                                 const float* __restrict__ cosT,
                                 const float* __restrict__ sinT,
                                 int nheads, int col0, float scl,
                                 __half* __restrict__ outH, int outw) {
    int idx = blockIdx.x * blockDim.x + threadIdx.x;
    int total = SEQ * nheads * 32;
    if (idx >= total) return;
    int i = idx % 32;
    int h = (idx / 32) % nheads;
    int s = idx / (32 * nheads);
    float c  = cosT[s * 32 + i];
    float sn = sinT[s * 32 + i];
    const float* row = QKV + (size_t)s * QKVN + col0 + h * HD;
    float t1 = row[i], t2 = row[i + 32];
    float r1 = (t1 * c - t2 * sn) * scl;
    float r2 = (t2 * c + t1 * sn) * scl;
    size_t o = (size_t)s * outw + h * HD + i;
    outH[o]      = __float2half(r1);
    outH[o + 32] = __float2half(r2);
}

__global__ void v_split_kernel(const float* __restrict__ QKV,
                               __half* __restrict__ Vh) {
    int idx = blockIdx.x * blockDim.x + threadIdx.x;
    if (idx >= SEQ * KVW) return;
    int s = idx / KVW, j = idx % KVW;
    Vh[idx] = __float2half(QKV[(size_t)s * QKVN + 1280 + j]);
}

// ---------------------------------------------------------------------------
// Tensor-core flash attention. 8 warps, BQ=128 (16 q-rows/warp), BK=64.
// QK^T: plain fp16 (Q pre-scaled by 1/8). P*V: plain fp16. fp32 accums.
// Double-buffered cp.async K/V loads; LPT; per-warp fully-masked-tile skip.
// ---------------------------------------------------------------------------
#define ATS 72
#define KTILE (64 * ATS)          // halves per 64-row tile
#define QTILE (128 * ATS)         // halves per 128-row Q tile
#define KVSTAGE (2 * KTILE)       // halves per KV stage (KsH, VsH)

__device__ __forceinline__ uint32_t pack_h2(float a, float b) {
    __half2 h = __floats2half2_rn(a, b);
    return *(uint32_t*)&h;
}

__global__ __launch_bounds__(256)
void attn_mma_kernel(const __half* __restrict__ Qh_,
                     const __half* __restrict__ Kh_,
                     const __half* __restrict__ Vh_,
                     __half* __restrict__ O) {
    extern __shared__ __half sm[];
    __half* QsH = sm;                       // [0, QTILE)
    // KV stages: stage s at sm + QTILE + s*KVSTAGE : {KsH, VsH}

    const int qt  = gridDim.x - 1 - blockIdx.x;   // LPT: longest first
    const int h   = blockIdx.y;
    const int kvh = h / (NH / NKV);
    const int tid = threadIdx.x;
    const int lane = tid & 31;
    const int wid = tid >> 5;                     // 0..7 -> q-rows wid*16

    const uint32_t kvb = smem_u32(sm + QTILE);

    // K/V tile load: 64 rows x 64 halves, 256 threads -> 16 halves/thread
    const int lr2 = tid >> 2;                     // 0..63
    const int lc2 = (tid & 3) * 16;               // 0,16,32,48
    auto load_kv = [&](int s, int kt) {
        size_t gbase = (size_t)(kt * 64 + lr2) * KVW + kvh * HD + lc2;
        uint32_t so = kvb + (uint32_t)s * (KVSTAGE * 2) + 2u * (lr2 * ATS + lc2);
        cp_async16(so,                  Kh_ + gbase);
        cp_async16(so + 16,             Kh_ + gbase + 8);
        cp_async16(so + KTILE * 2,      Vh_ + gbase);
        cp_async16(so + KTILE * 2 + 16, Vh_ + gbase + 8);
    };

    // Load Q tile (128 rows x 64 halves, 32 halves/thread)
    {
        const int lr = tid >> 1;                  // 0..127
        const int lc = (tid & 1) * 32;
        const __half* sh = Qh_ + (size_t)(qt * 128 + lr) * DMODEL + h * HD + lc;
        #pragma unroll
        for (int j = 0; j < 4; j++)
            *(uint4*)(QsH + lr * ATS + lc + 8 * j) = *(const uint4*)(sh + 8 * j);
    }
    load_kv(0, 0); cp_commit();
    __syncthreads();

    const uint32_t qsh = smem_u32(QsH);

    const int a_lrow = lane & 15, a_lcol = (lane >> 4) << 3;
    const int b_noff = (lane & 7) + ((lane >> 4) << 3);
    const int b_koff = ((lane >> 3) & 1) << 3;

    uint32_t qf[4][4];
    #pragma unroll
    for (int kk = 0; kk < 4; kk++) {
        uint32_t ao = 2u * ((wid * 16 + a_lrow) * ATS + kk * 16 + a_lcol);
        ldsm_x4(qf[kk], qsh + ao);
    }

    const int g = lane >> 2, t = lane & 3;
    const int qg0 = qt * 128 + wid * 16 + g;
    const int qg1 = qg0 + 8;

    float o[8][4];
    #pragma unroll
    for (int nj = 0; nj < 8; nj++)
        #pragma unroll
        for (int e = 0; e < 4; e++) o[nj][e] = 0.f;
    float m0 = -INFINITY, m1 = -INFINITY, l0 = 0.f, l1 = 0.f;

    const int nkt = 2 * qt + 2;    // k-tiles covering q rows [128qt, 128qt+127]

    for (int kt = 0; kt < nkt; kt++) {
        cp_wait<0>();
        __syncthreads();
        if (kt + 1 < nkt) { load_kv((kt + 1) & 1, kt + 1); cp_commit(); }

        // Skip warp-tiles that are entirely above the diagonal
        const bool active = (kt * 64 <= qg1);
        if (active) {
            const uint32_t ksh = kvb + (uint32_t)(kt & 1) * (KVSTAGE * 2);
            const uint32_t vsh = ksh + KTILE * 2;

            float s[8][4];
            #pragma unroll
            for (int nj = 0; nj < 8; nj++)
                #pragma unroll
                for (int e = 0; e < 4; e++) s[nj][e] = 0.f;

            #pragma unroll
            for (int nj16 = 0; nj16 < 4; nj16++) {
                #pragma unroll
                for (int kk = 0; kk < 4; kk++) {
                    uint32_t bo = 2u * ((nj16 * 16 + b_noff) * ATS + kk * 16 + b_koff);
                    uint32_t bh[4];
                    ldsm_x4(bh, ksh + bo);
                    mma16816(s[2 * nj16],     qf[kk], bh[0], bh[1]);
                    mma16816(s[2 * nj16 + 1], qf[kk], bh[2], bh[3]);
                }
            }

            float mt0 = m0, mt1 = m1;
            const bool need_mask = (kt * 64 + 63 > qg0);
            #pragma unroll
            for (int nj = 0; nj < 8; nj++) {
                int kg = kt * 64 + nj * 8 + 2 * t;
                if (need_mask) {
                    if (kg     > qg0) s[nj][0] = -INFINITY;
                    if (kg + 1 > qg0) s[nj][1] = -INFINITY;
                    if (kg     > qg1) s[nj][2] = -INFINITY;
                    if (kg + 1 > qg1) s[nj][3] = -INFINITY;
                }
                mt0 = fmaxf(mt0, fmaxf(s[nj][0], s[nj][1]));
                mt1 = fmaxf(mt1, fmaxf(s[nj][2], s[nj][3]));
            }
            mt0 = fmaxf(mt0, __shfl_xor_sync(0xffffffffu, mt0, 1));
            mt0 = fmaxf(mt0, __shfl_xor_sync(0xffffffffu, mt0, 2));
            mt1 = fmaxf(mt1, __shfl_xor_sync(0xffffffffu, mt1, 1));
            mt1 = fmaxf(mt1, __shfl_xor_sync(0xffffffffu, mt1, 2));

            float corr0 = __expf(m0 - mt0);
            float corr1 = __expf(m1 - mt1);
            float ps0 = 0.f, ps1 = 0.f;
            #pragma unroll
            for (int nj = 0; nj < 8; nj++) {
                s[nj][0] = __expf(s[nj][0] - mt0);
                s[nj][1] = __expf(s[nj][1] - mt0);
                s[nj][2] = __expf(s[nj][2] - mt1);
                s[nj][3] = __expf(s[nj][3] - mt1);
                ps0 += s[nj][0] + s[nj][1];
                ps1 += s[nj][2] + s[nj][3];
            }
            ps0 += __shfl_xor_sync(0xffffffffu, ps0, 1);
            ps0 += __shfl_xor_sync(0xffffffffu, ps0, 2);
            ps1 += __shfl_xor_sync(0xffffffffu, ps1, 1);
            ps1 += __shfl_xor_sync(0xffffffffu, ps1, 2);
            l0 = l0 * corr0 + ps0;  m0 = mt0;
            l1 = l1 * corr1 + ps1;  m1 = mt1;

            #pragma unroll
            for (int nj = 0; nj < 8; nj++) {
                o[nj][0] *= corr0;  o[nj][1] *= corr0;
                o[nj][2] *= corr1;  o[nj][3] *= corr1;
            }

            #pragma unroll
            for (int kk = 0; kk < 4; kk++) {
                uint32_t pah[4];
                pah[0] = pack_h2(s[2 * kk][0],     s[2 * kk][1]);
                pah[1] = pack_h2(s[2 * kk][2],     s[2 * kk][3]);
                pah[2] = pack_h2(s[2 * kk + 1][0], s[2 * kk + 1][1]);
                pah[3] = pack_h2(s[2 * kk + 1][2], s[2 * kk + 1][3]);
                #pragma unroll
                for (int dj16 = 0; dj16 < 4; dj16++) {
                    uint32_t vo = 2u * ((kk * 16 + (lane & 15)) * ATS +
                                        dj16 * 16 + ((lane >> 4) << 3));
                    uint32_t bh[4];
                    ldsm_x4_trans(bh, vsh + vo);
                    mma16816(o[2 * dj16],     pah, bh[0], bh[1]);
                    mma16816(o[2 * dj16 + 1], pah, bh[2], bh[3]);
                }
            }
        }
        __syncthreads();   // protect current stage before it is reloaded (kt+2)
    }

    float inv0 = 1.f / l0, inv1 = 1.f / l1;
    #pragma unroll
    for (int nj = 0; nj < 8; nj++) {
        int col = h * HD + nj * 8 + 2 * t;
        __half2 v0 = __floats2half2_rn(o[nj][0] * inv0, o[nj][1] * inv0);
        __half2 v1 = __floats2half2_rn(o[nj][2] * inv1, o[nj][3] * inv1);
        *(__half2*)(O + (size_t)qg0 * DMODEL + col) = v0;
        *(__half2*)(O + (size_t)qg1 * DMODEL + col) = v1;
    }
}

// ---------------------------------------------------------------------------
// Launch. Inputs: x, rope_cos, rope_sin, Wq, Wk, Wv, Wo
// ---------------------------------------------------------------------------
extern "C" void kernel_launch(void* const* d_in, const int* in_sizes, int n_in,
                              void* d_out, int out_size) {
    const float* x    = (const float*)d_in[0];
    const float* cosT = (const float*)d_in[1];
    const float* sinT = (const float*)d_in[2];
    const float* Wq   = (const float*)d_in[3];
    const float* Wk   = (const float*)d_in[4];
    const float* Wv   = (const float*)d_in[5];
    const float* Wo   = (const float*)d_in[6];
    float* out = (float*)d_out;

    __half *x16, *wqkv16, *wo16, *o16, *qh, *kh, *vh;
    float *qkv;
    cudaGetSymbolAddress((void**)&x16,    g_x16);
    cudaGetSymbolAddress((void**)&wqkv16, g_Wqkv16);
    cudaGetSymbolAddress((void**)&wo16,   g_Wo16);
    cudaGetSymbolAddress((void**)&qkv,    g_QKV);
    cudaGetSymbolAddress((void**)&o16,    g_O16);
    cudaGetSymbolAddress((void**)&qh, g_Qh);
    cudaGetSymbolAddress((void**)&kh, g_Kh);
    cudaGetSymbolAddress((void**)&vh, g_Vh);

    const int attn_smem = (QTILE + 2 * KVSTAGE) * 2;   // 55296 bytes
    cudaFuncSetAttribute(attn_mma_kernel,
                         cudaFuncAttributeMaxDynamicSharedMemorySize, attn_smem);

    // Converts (x, fused Wqkv, Wo)
    {
        int n = SEQ * DMODEL;
        conv_f16_kernel<<<(n + 255) / 256, 256>>>(x, x16, n);
        int nw = DMODEL * QKVN;
        conv_wqkv_kernel<<<(nw + 255) / 256, 256>>>(Wq, Wk, Wv, wqkv16);
        int no = DMODEL * DMODEL;
        conv_f16_kernel<<<(no + 255) / 256, 256>>>(Wo, wo16, no);
    }

    // Fused QKV projection: TBN=64 -> grid 384
    gemm_hmma_kernel<64><<<dim3(QKVN / 64, SEQ / BM), 256>>>(
        x16, wqkv16, qkv, SEQ, QKVN, DMODEL);

    // RoPE + converts: Q pre-scaled by 1/8 (exact), K unscaled, V straight
    {
        int totq = SEQ * NH * 32;
        rope_conv_kernel<<<(totq + 255) / 256, 256>>>(
            qkv, cosT, sinT, NH, 0, 0.125f, qh, DMODEL);
        int totk = SEQ * NKV * 32;
        rope_conv_kernel<<<(totk + 255) / 256, 256>>>(
            qkv, cosT, sinT, NKV, 1024, 1.0f, kh, KVW);
        int totv = SEQ * KVW;
        v_split_kernel<<<(totv + 255) / 256, 256>>>(qkv, vh);
    }

    // Tensor-core flash attention: BQ=128, 8 warps
    {
        dim3 grid(SEQ / 128, NH);
        attn_mma_kernel<<<grid, 256, attn_smem>>>(qh, kh, vh, o16);
    }

    // Output projection: TBN=128 -> grid 128 (single wave)
    gemm_hmma_kernel<128><<<dim3(DMODEL / 128, SEQ / BM), 256>>>(
        o16, wo16, out, SEQ, DMODEL, DMODEL);
}

// round 17
// speedup vs baseline: 1.0299x; 1.0299x over previous
#include <cuda_runtime.h>
#include <cuda_fp16.h>
#include <math.h>
#include <stdint.h>

// Problem constants
#define SEQ    2048
#define DMODEL 1024
#define NH     16
#define NKV    4
#define HD     64
#define QKVN   1536         // fused Q(1024) + K(256) + V(256)
#define KVW    256          // NKV*HD

// ---------------------------------------------------------------------------
// Scratch (device globals)
// ---------------------------------------------------------------------------
__device__ __half g_x16[SEQ * DMODEL];
__device__ __half g_Wqkv16[DMODEL * QKVN];
__device__ __half g_Wo16[DMODEL * DMODEL];
__device__ float  g_QKV[SEQ * QKVN];
__device__ __half g_O16[SEQ * DMODEL];
__device__ __half g_Qh[SEQ * DMODEL];          // pre-scaled by 1/8
__device__ __half g_Kh[SEQ * KVW];
__device__ __half g_Vh[SEQ * KVW];

__device__ __forceinline__ uint32_t smem_u32(const void* p) {
    return (uint32_t)__cvta_generic_to_shared(p);
}

// ---------------------------------------------------------------------------
// cp.async helpers
// ---------------------------------------------------------------------------
__device__ __forceinline__ void cp_async16(uint32_t dst, const void* src) {
    asm volatile("cp.async.cg.shared.global [%0], [%1], 16;"
                 :: "r"(dst), "l"(src));
}
__device__ __forceinline__ void cp_commit() {
    asm volatile("cp.async.commit_group;");
}
template <int N>
__device__ __forceinline__ void cp_wait() {
    asm volatile("cp.async.wait_group %0;" :: "n"(N));
}

// ---------------------------------------------------------------------------
// Converts
// ---------------------------------------------------------------------------
__global__ void conv_f16_kernel(const float* __restrict__ in,
                                __half* __restrict__ out, int n) {
    int i = blockIdx.x * blockDim.x + threadIdx.x;
    if (i < n) out[i] = __float2half(in[i]);
}

__global__ void conv_wqkv_kernel(const float* __restrict__ Wq,
                                 const float* __restrict__ Wk,
                                 const float* __restrict__ Wv,
                                 __half* __restrict__ out) {
    int i = blockIdx.x * blockDim.x + threadIdx.x;
    if (i >= DMODEL * QKVN) return;
    int k = i / QKVN, n = i % QKVN;
    float v;
    if (n < 1024)       v = Wq[k * 1024 + n];
    else if (n < 1280)  v = Wk[k * 256 + (n - 1024)];
    else                v = Wv[k * 256 + (n - 1280)];
    out[i] = __float2half(v);
}

// ---------------------------------------------------------------------------
// HMMA GEMM, 2-stage cp.async, BK=64 (per-chunk compute covers L2 latency).
// C[M,N] = A[M,K](f16) @ B[K,N](f16), f32 accum. B row-major via ldsm.trans.
// 256 threads, 8 warps (2 x 4), warp tile 64 x (TBN/4). Dynamic smem.
// ---------------------------------------------------------------------------
#define BM 128
#define GBK 64
#define GASTR 72     // A smem stride (halves): 64 data + 8 pad

__device__ __forceinline__ void ldsm_x4(uint32_t* r, uint32_t addr) {
    asm volatile("ldmatrix.sync.aligned.m8n8.x4.shared.b16 {%0,%1,%2,%3}, [%4];"
                 : "=r"(r[0]), "=r"(r[1]), "=r"(r[2]), "=r"(r[3]) : "r"(addr));
}
__device__ __forceinline__ void ldsm_x4_trans(uint32_t* r, uint32_t addr) {
    asm volatile("ldmatrix.sync.aligned.m8n8.x4.trans.shared.b16 {%0,%1,%2,%3}, [%4];"
                 : "=r"(r[0]), "=r"(r[1]), "=r"(r[2]), "=r"(r[3]) : "r"(addr));
}
__device__ __forceinline__ void mma16816(float* c, const uint32_t* a,
                                         uint32_t b0, uint32_t b1) {
    asm volatile(
        "mma.sync.aligned.m16n8k16.row.col.f32.f16.f16.f32 "
        "{%0,%1,%2,%3}, {%4,%5,%6,%7}, {%8,%9}, {%0,%1,%2,%3};"
        : "+f"(c[0]), "+f"(c[1]), "+f"(c[2]), "+f"(c[3])
        : "r"(a[0]), "r"(a[1]), "r"(a[2]), "r"(a[3]), "r"(b0), "r"(b1));
}

template <int TBN>
__global__ __launch_bounds__(256)
void gemm_hmma_kernel(const __half* __restrict__ A,
                      const __half* __restrict__ B,
                      float* __restrict__ C, int M, int N, int K) {
    constexpr int BSTRT = TBN + 8;
    constexpr int WN    = TBN / 4;         // warp N extent (32 or 16)
    constexpr int FN    = WN / 8;          // n-fragments per warp
    constexpr int P16   = WN / 16;         // 16-wide ldsm groups
    constexpr int COLS8 = TBN / 8;         // 8-half column groups per B row
    constexpr int AS_SZ = BM * GASTR;      // halves per A stage
    constexpr int BS_SZ = GBK * BSTRT;     // halves per B stage
    constexpr int NBI   = TBN / 32;        // B cp.async iters per thread

    extern __shared__ __half smg[];
    // layout: As[0], As[1], Bs[0], Bs[1]
    const uint32_t asS[2] = { smem_u32(smg), smem_u32(smg + AS_SZ) };
    const uint32_t bsS[2] = { smem_u32(smg + 2 * AS_SZ),
                              smem_u32(smg + 2 * AS_SZ + BS_SZ) };

    const int tid = threadIdx.x;
    const int lane = tid & 31;
    const int wid = tid >> 5;
    const int wm0 = (wid >> 2) * 64;
    const int wn0 = (wid & 3) * WN;
    const int row0 = blockIdx.y * BM;
    const int col0 = blockIdx.x * TBN;

    float acc[4][FN][4];
    #pragma unroll
    for (int i = 0; i < 4; i++)
        #pragma unroll
        for (int j = 0; j < FN; j++)
            #pragma unroll
            for (int k = 0; k < 4; k++) acc[i][j][k] = 0.f;

    const int a_lrow = lane & 15, a_lcol = (lane >> 4) << 3;
    const int b_krow = lane & 15, b_ncol = (lane >> 4) << 3;

    const int nchunks = K / GBK;           // 16

    auto load_stage = [&](int st, int c) {
        int k0 = c * GBK;
        // A tile: 128 rows x 64 halves = 1024 x 16B, 4 per thread
        #pragma unroll
        for (int i = 0; i < 4; i++) {
            int idx = tid + i * 256;
            int r = idx >> 3, c8 = idx & 7;
            cp_async16(asS[st] + 2u * (r * GASTR + c8 * 8),
                       A + (size_t)(row0 + r) * K + k0 + c8 * 8);
        }
        // B tile: 64 rows x TBN halves, NBI per thread
        #pragma unroll
        for (int i = 0; i < NBI; i++) {
            int idx = tid + i * 256;
            int r = idx / COLS8, c8 = idx % COLS8;
            cp_async16(bsS[st] + 2u * (r * BSTRT + c8 * 8),
                       B + (size_t)(k0 + r) * N + col0 + c8 * 8);
        }
    };

    load_stage(0, 0);
    cp_commit();

    for (int c = 0; c < nchunks; c++) {
        const int st = c & 1;
        if (c + 1 < nchunks) {
            load_stage(st ^ 1, c + 1);
            cp_commit();
            cp_wait<1>();
        } else {
            cp_wait<0>();
        }
        __syncthreads();

        const uint32_t asb = asS[st];
        const uint32_t bsb = bsS[st];
        #pragma unroll
        for (int ks = 0; ks < 4; ks++) {
            uint32_t af[4][4], bf[P16][4];
            #pragma unroll
            for (int fm = 0; fm < 4; fm++) {
                uint32_t addr = asb +
                    2u * ((wm0 + fm * 16 + a_lrow) * GASTR + ks * 16 + a_lcol);
                ldsm_x4(af[fm], addr);
            }
            #pragma unroll
            for (int p = 0; p < P16; p++) {
                uint32_t addr = bsb +
                    2u * ((ks * 16 + b_krow) * BSTRT + wn0 + p * 16 + b_ncol);
                ldsm_x4_trans(bf[p], addr);
            }
            #pragma unroll
            for (int fm = 0; fm < 4; fm++)
                #pragma unroll
                for (int fn = 0; fn < FN; fn++)
                    mma16816(acc[fm][fn], af[fm],
                             bf[fn >> 1][(fn & 1) * 2],
                             bf[fn >> 1][(fn & 1) * 2 + 1]);
        }
        __syncthreads();
    }

    const int g = lane >> 2, t = lane & 3;
    #pragma unroll
    for (int fm = 0; fm < 4; fm++) {
        #pragma unroll
        for (int fn = 0; fn < FN; fn++) {
            int r = row0 + wm0 + fm * 16 + g;
            int cc = col0 + wn0 + fn * 8 + 2 * t;
            *(float2*)(C + (size_t)r * N + cc) =
                make_float2(acc[fm][fn][0], acc[fm][fn][1]);
            *(float2*)(C + (size_t)(r + 8) * N + cc) =
                make_float2(acc[fm][fn][2], acc[fm][fn][3]);
        }
    }
}

// ---------------------------------------------------------------------------
// RoPE + fp16 convert with optional pre-scale (Q: 1/8, K: 1).
// ---------------------------------------------------------------------------
__global__ void rope_conv_kernel(const float* __restrict__ QKV,
                                 const float* __restrict__ cosT,
                                 const float* __restrict__ sinT,
                                 int nheads, int col0, float scl,
                                 __half* __restrict__ outH, int outw) {
    int idx = blockIdx.x * blockDim.x + threadIdx.x;
    int total = SEQ * nheads * 32;
    if (idx >= total) return;
    int i = idx % 32;
    int h = (idx / 32) % nheads;
    int s = idx / (32 * nheads);
    float c  = cosT[s * 32 + i];
    float sn = sinT[s * 32 + i];
    const float* row = QKV + (size_t)s * QKVN + col0 + h * HD;
    float t1 = row[i], t2 = row[i + 32];
    float r1 = (t1 * c - t2 * sn) * scl;
    float r2 = (t2 * c + t1 * sn) * scl;
    size_t o = (size_t)s * outw + h * HD + i;
    outH[o]      = __float2half(r1);
    outH[o + 32] = __float2half(r2);
}

__global__ void v_split_kernel(const float* __restrict__ QKV,
                               __half* __restrict__ Vh) {
    int idx = blockIdx.x * blockDim.x + threadIdx.x;
    if (idx >= SEQ * KVW) return;
    int s = idx / KVW, j = idx % KVW;
    Vh[idx] = __float2half(QKV[(size_t)s * QKVN + 1280 + j]);
}

// ---------------------------------------------------------------------------
// Tensor-core flash attention. 8 warps, BQ=128 (16 q-rows/warp), BK=64.
// QK^T: plain fp16 (Q pre-scaled by 1/8). P*V: plain fp16. fp32 accums.
// Double-buffered cp.async K/V loads; LPT; per-warp fully-masked-tile skip.
// ---------------------------------------------------------------------------
#define ATS 72
#define KTILE (64 * ATS)          // halves per 64-row tile
#define QTILE (128 * ATS)         // halves per 128-row Q tile
#define KVSTAGE (2 * KTILE)       // halves per KV stage (KsH, VsH)

__device__ __forceinline__ uint32_t pack_h2(float a, float b) {
    __half2 h = __floats2half2_rn(a, b);
    return *(uint32_t*)&h;
}

__global__ __launch_bounds__(256)
void attn_mma_kernel(const __half* __restrict__ Qh_,
                     const __half* __restrict__ Kh_,
                     const __half* __restrict__ Vh_,
                     __half* __restrict__ O) {
    extern __shared__ __half sm[];
    __half* QsH = sm;                       // [0, QTILE)
    // KV stages: stage s at sm + QTILE + s*KVSTAGE : {KsH, VsH}

    const int qt  = gridDim.x - 1 - blockIdx.x;   // LPT: longest first
    const int h   = blockIdx.y;
    const int kvh = h / (NH / NKV);
    const int tid = threadIdx.x;
    const int lane = tid & 31;
    const int wid = tid >> 5;                     // 0..7 -> q-rows wid*16

    const uint32_t kvb = smem_u32(sm + QTILE);

    // K/V tile load: 64 rows x 64 halves, 256 threads -> 16 halves/thread
    const int lr2 = tid >> 2;                     // 0..63
    const int lc2 = (tid & 3) * 16;               // 0,16,32,48
    auto load_kv = [&](int s, int kt) {
        size_t gbase = (size_t)(kt * 64 + lr2) * KVW + kvh * HD + lc2;
        uint32_t so = kvb + (uint32_t)s * (KVSTAGE * 2) + 2u * (lr2 * ATS + lc2);
        cp_async16(so,                  Kh_ + gbase);
        cp_async16(so + 16,             Kh_ + gbase + 8);
        cp_async16(so + KTILE * 2,      Vh_ + gbase);
        cp_async16(so + KTILE * 2 + 16, Vh_ + gbase + 8);
    };

    // Load Q tile (128 rows x 64 halves, 32 halves/thread)
    {
        const int lr = tid >> 1;                  // 0..127
        const int lc = (tid & 1) * 32;
        const __half* sh = Qh_ + (size_t)(qt * 128 + lr) * DMODEL + h * HD + lc;
        #pragma unroll
        for (int j = 0; j < 4; j++)
            *(uint4*)(QsH + lr * ATS + lc + 8 * j) = *(const uint4*)(sh + 8 * j);
    }
    load_kv(0, 0); cp_commit();
    __syncthreads();

    const uint32_t qsh = smem_u32(QsH);

    const int a_lrow = lane & 15, a_lcol = (lane >> 4) << 3;
    const int b_noff = (lane & 7) + ((lane >> 4) << 3);
    const int b_koff = ((lane >> 3) & 1) << 3;

    uint32_t qf[4][4];
    #pragma unroll
    for (int kk = 0; kk < 4; kk++) {
        uint32_t ao = 2u * ((wid * 16 + a_lrow) * ATS + kk * 16 + a_lcol);
        ldsm_x4(qf[kk], qsh + ao);
    }

    const int g = lane >> 2, t = lane & 3;
    const int qg0 = qt * 128 + wid * 16 + g;
    const int qg1 = qg0 + 8;

    float o[8][4];
    #pragma unroll
    for (int nj = 0; nj < 8; nj++)
        #pragma unroll
        for (int e = 0; e < 4; e++) o[nj][e] = 0.f;
    float m0 = -INFINITY, m1 = -INFINITY, l0 = 0.f, l1 = 0.f;

    const int nkt = 2 * qt + 2;    // k-tiles covering q rows [128qt, 128qt+127]

    for (int kt = 0; kt < nkt; kt++) {
        cp_wait<0>();
        __syncthreads();
        if (kt + 1 < nkt) { load_kv((kt + 1) & 1, kt + 1); cp_commit(); }

        // Skip warp-tiles that are entirely above the diagonal
        const bool active = (kt * 64 <= qg1);
        if (active) {
            const uint32_t ksh = kvb + (uint32_t)(kt & 1) * (KVSTAGE * 2);
            const uint32_t vsh = ksh + KTILE * 2;

            float s[8][4];
            #pragma unroll
            for (int nj = 0; nj < 8; nj++)
                #pragma unroll
                for (int e = 0; e < 4; e++) s[nj][e] = 0.f;

            #pragma unroll
            for (int nj16 = 0; nj16 < 4; nj16++) {
                #pragma unroll
                for (int kk = 0; kk < 4; kk++) {
                    uint32_t bo = 2u * ((nj16 * 16 + b_noff) * ATS + kk * 16 + b_koff);
                    uint32_t bh[4];
                    ldsm_x4(bh, ksh + bo);
                    mma16816(s[2 * nj16],     qf[kk], bh[0], bh[1]);
                    mma16816(s[2 * nj16 + 1], qf[kk], bh[2], bh[3]);
                }
            }

            float mt0 = m0, mt1 = m1;
            const bool need_mask = (kt * 64 + 63 > qg0);
            #pragma unroll
            for (int nj = 0; nj < 8; nj++) {
                int kg = kt * 64 + nj * 8 + 2 * t;
                if (need_mask) {
                    if (kg     > qg0) s[nj][0] = -INFINITY;
                    if (kg + 1 > qg0) s[nj][1] = -INFINITY;
                    if (kg     > qg1) s[nj][2] = -INFINITY;
                    if (kg + 1 > qg1) s[nj][3] = -INFINITY;
                }
                mt0 = fmaxf(mt0, fmaxf(s[nj][0], s[nj][1]));
                mt1 = fmaxf(mt1, fmaxf(s[nj][2], s[nj][3]));
            }
            mt0 = fmaxf(mt0, __shfl_xor_sync(0xffffffffu, mt0, 1));
            mt0 = fmaxf(mt0, __shfl_xor_sync(0xffffffffu, mt0, 2));
            mt1 = fmaxf(mt1, __shfl_xor_sync(0xffffffffu, mt1, 1));
            mt1 = fmaxf(mt1, __shfl_xor_sync(0xffffffffu, mt1, 2));

            float corr0 = __expf(m0 - mt0);
            float corr1 = __expf(m1 - mt1);
            float ps0 = 0.f, ps1 = 0.f;
            #pragma unroll
            for (int nj = 0; nj < 8; nj++) {
                s[nj][0] = __expf(s[nj][0] - mt0);
                s[nj][1] = __expf(s[nj][1] - mt0);
                s[nj][2] = __expf(s[nj][2] - mt1);
                s[nj][3] = __expf(s[nj][3] - mt1);
                ps0 += s[nj][0] + s[nj][1];
                ps1 += s[nj][2] + s[nj][3];
            }
            ps0 += __shfl_xor_sync(0xffffffffu, ps0, 1);
            ps0 += __shfl_xor_sync(0xffffffffu, ps0, 2);
            ps1 += __shfl_xor_sync(0xffffffffu, ps1, 1);
            ps1 += __shfl_xor_sync(0xffffffffu, ps1, 2);
            l0 = l0 * corr0 + ps0;  m0 = mt0;
            l1 = l1 * corr1 + ps1;  m1 = mt1;

            #pragma unroll
            for (int nj = 0; nj < 8; nj++) {
                o[nj][0] *= corr0;  o[nj][1] *= corr0;
                o[nj][2] *= corr1;  o[nj][3] *= corr1;
            }

            #pragma unroll
            for (int kk = 0; kk < 4; kk++) {
                uint32_t pah[4];
                pah[0] = pack_h2(s[2 * kk][0],     s[2 * kk][1]);
                pah[1] = pack_h2(s[2 * kk][2],     s[2 * kk][3]);
                pah[2] = pack_h2(s[2 * kk + 1][0], s[2 * kk + 1][1]);
                pah[3] = pack_h2(s[2 * kk + 1][2], s[2 * kk + 1][3]);
                #pragma unroll
                for (int dj16 = 0; dj16 < 4; dj16++) {
                    uint32_t vo = 2u * ((kk * 16 + (lane & 15)) * ATS +
                                        dj16 * 16 + ((lane >> 4) << 3));
                    uint32_t bh[4];
                    ldsm_x4_trans(bh, vsh + vo);
                    mma16816(o[2 * dj16],     pah, bh[0], bh[1]);
                    mma16816(o[2 * dj16 + 1], pah, bh[2], bh[3]);
                }
            }
        }
        __syncthreads();   // protect current stage before it is reloaded (kt+2)
    }

    float inv0 = 1.f / l0, inv1 = 1.f / l1;
    #pragma unroll
    for (int nj = 0; nj < 8; nj++) {
        int col = h * HD + nj * 8 + 2 * t;
        __half2 v0 = __floats2half2_rn(o[nj][0] * inv0, o[nj][1] * inv0);
        __half2 v1 = __floats2half2_rn(o[nj][2] * inv1, o[nj][3] * inv1);
        *(__half2*)(O + (size_t)qg0 * DMODEL + col) = v0;
        *(__half2*)(O + (size_t)qg1 * DMODEL + col) = v1;
    }
}

// ---------------------------------------------------------------------------
// Launch. Inputs: x, rope_cos, rope_sin, Wq, Wk, Wv, Wo
// ---------------------------------------------------------------------------
extern "C" void kernel_launch(void* const* d_in, const int* in_sizes, int n_in,
                              void* d_out, int out_size) {
    const float* x    = (const float*)d_in[0];
    const float* cosT = (const float*)d_in[1];
    const float* sinT = (const float*)d_in[2];
    const float* Wq   = (const float*)d_in[3];
    const float* Wk   = (const float*)d_in[4];
    const float* Wv   = (const float*)d_in[5];
    const float* Wo   = (const float*)d_in[6];
    float* out = (float*)d_out;

    __half *x16, *wqkv16, *wo16, *o16, *qh, *kh, *vh;
    float *qkv;
    cudaGetSymbolAddress((void**)&x16,    g_x16);
    cudaGetSymbolAddress((void**)&wqkv16, g_Wqkv16);
    cudaGetSymbolAddress((void**)&wo16,   g_Wo16);
    cudaGetSymbolAddress((void**)&qkv,    g_QKV);
    cudaGetSymbolAddress((void**)&o16,    g_O16);
    cudaGetSymbolAddress((void**)&qh, g_Qh);
    cudaGetSymbolAddress((void**)&kh, g_Kh);
    cudaGetSymbolAddress((void**)&vh, g_Vh);

    // GEMM dynamic smem: 2 A stages (128x72) + 2 B stages (64x(TBN+8)), halves
    const int gemm64_smem  = (2 * BM * GASTR + 2 * GBK * (64 + 8)) * 2;   // 55296
    const int gemm128_smem = (2 * BM * GASTR + 2 * GBK * (128 + 8)) * 2;  // 71680
    cudaFuncSetAttribute(gemm_hmma_kernel<64>,
                         cudaFuncAttributeMaxDynamicSharedMemorySize, gemm64_smem);
    cudaFuncSetAttribute(gemm_hmma_kernel<128>,
                         cudaFuncAttributeMaxDynamicSharedMemorySize, gemm128_smem);

    const int attn_smem = (QTILE + 2 * KVSTAGE) * 2;   // 55296 bytes
    cudaFuncSetAttribute(attn_mma_kernel,
                         cudaFuncAttributeMaxDynamicSharedMemorySize, attn_smem);

    // Converts (x, fused Wqkv, Wo)
    {
        int n = SEQ * DMODEL;
        conv_f16_kernel<<<(n + 255) / 256, 256>>>(x, x16, n);
        int nw = DMODEL * QKVN;
        conv_wqkv_kernel<<<(nw + 255) / 256, 256>>>(Wq, Wk, Wv, wqkv16);
        int no = DMODEL * DMODEL;
        conv_f16_kernel<<<(no + 255) / 256, 256>>>(Wo, wo16, no);
    }

    // Fused QKV projection: TBN=64 -> grid 384
    gemm_hmma_kernel<64><<<dim3(QKVN / 64, SEQ / BM), 256, gemm64_smem>>>(
        x16, wqkv16, qkv, SEQ, QKVN, DMODEL);

    // RoPE + converts: Q pre-scaled by 1/8 (exact), K unscaled, V straight
    {
        int totq = SEQ * NH * 32;
        rope_conv_kernel<<<(totq + 255) / 256, 256>>>(
            qkv, cosT, sinT, NH, 0, 0.125f, qh, DMODEL);
        int totk = SEQ * NKV * 32;
        rope_conv_kernel<<<(totk + 255) / 256, 256>>>(
            qkv, cosT, sinT, NKV, 1024, 1.0f, kh, KVW);
        int totv = SEQ * KVW;
        v_split_kernel<<<(totv + 255) / 256, 256>>>(qkv, vh);
    }

    // Tensor-core flash attention: BQ=128, 8 warps
    {
        dim3 grid(SEQ / 128, NH);
        attn_mma_kernel<<<grid, 256, attn_smem>>>(qh, kh, vh, o16);
    }

    // Output projection: TBN=128 -> grid 128 (single wave)
    gemm_hmma_kernel<128><<<dim3(DMODEL / 128, SEQ / BM), 256, gemm128_smem>>>(
        o16, wo16, out, SEQ, DMODEL, DMODEL);
}